// round 3
// baseline (speedup 1.0000x reference)
#include <cuda_runtime.h>

// ---------------- problem constants (fixed shapes) ----------------
#define NN 50000
#define EE 600000
#define DD 128
#define HH 256
#define LL 6

// ---------------- device scratch (no allocs allowed) ----------------
__device__ __align__(128) float d_h [NN * DD];      // node features
__device__ __align__(128) float d_g [NN * DD];      // relu(LN(h)); reused as head buf
__device__ __align__(128) float d_pq[NN * 2 * DD];  // [p | q] per node
__device__ __align__(128) float d_no[NN * DD];      // agg + g (GENConv pre-MLP)
__device__ __align__(128) float d_z [NN * HH];      // MLP hidden
__device__ int d_deg[NN];
__device__ int d_rowptr[NN + 1];
__device__ int d_cursor[NN];
__device__ int d_colsrc[EE];
__device__ int d_is64;  // 1 if edge_index is int64, 0 if int32

// Buffer ids: 0 = use passed pointer, 1 = d_h, 2 = d_g, 3 = d_no, 4 = d_z
__device__ __forceinline__ const float* resolve_c(const float* p, int id) {
    switch (id) {
        case 1: return d_h;
        case 2: return d_g;
        case 3: return d_no;
        case 4: return d_z;
        default: return p;
    }
}
__device__ __forceinline__ float* resolve_m(float* p, int id) {
    switch (id) {
        case 1: return d_h;
        case 2: return d_g;
        case 3: return d_no;
        case 4: return d_z;
        default: return p;
    }
}

// ---------------- edge index decode (dtype-agnostic) ----------------
__device__ __forceinline__ int edge_at(const void* ei, int is64, size_t pos) {
    int v;
    if (is64) v = (int)((const long long*)ei)[pos];
    else      v = ((const int*)ei)[pos];
    // defensive clamp: wrong dtype guess must not crash
    if (v < 0) v = 0;
    if (v >= NN) v = NN - 1;
    return v;
}

// Single-block probe: if first 1024 int64-interpretations are all in [0, NN),
// the buffer is int64; otherwise int32.
__global__ void k_probe(const void* ei) {
    __shared__ int bad;
    if (threadIdx.x == 0) bad = 0;
    __syncthreads();
    const long long* p = (const long long*)ei;
    // int64 buffer has 2*EE elements; sampling 1024 is safe for either dtype
    // (int32 buffer of 2*EE int32s = EE int64-sized slots, 1024 << EE).
    for (int i = threadIdx.x; i < 1024; i += blockDim.x) {
        long long v = p[i];
        if (v < 0 || v >= NN) bad = 1;
    }
    __syncthreads();
    if (threadIdx.x == 0) d_is64 = bad ? 0 : 1;
}

// ---------------- CSR build ----------------
__global__ void k_zero_deg() {
    int i = blockIdx.x * blockDim.x + threadIdx.x;
    if (i < NN) d_deg[i] = 0;
}

__global__ void k_count(const void* __restrict__ ei) {
    int e = blockIdx.x * blockDim.x + threadIdx.x;
    if (e < EE) {
        int dst = edge_at(ei, d_is64, (size_t)EE + e);
        atomicAdd(&d_deg[dst], 1);
    }
}

__global__ void k_scan() {
    __shared__ int sm[1024];
    const int CH = (NN + 1023) / 1024;  // 49
    int tid = threadIdx.x;
    int start = tid * CH;
    int endi = min(start + CH, NN);
    int s = 0;
    for (int i = start; i < endi; i++) s += d_deg[i];
    sm[tid] = s;
    __syncthreads();
    // Hillis-Steele inclusive scan
    for (int off = 1; off < 1024; off <<= 1) {
        int v = (tid >= off) ? sm[tid - off] : 0;
        __syncthreads();
        sm[tid] += v;
        __syncthreads();
    }
    int run = (tid > 0) ? sm[tid - 1] : 0;
    for (int i = start; i < endi; i++) {
        d_rowptr[i] = run;
        d_cursor[i] = run;
        run += d_deg[i];
    }
    if (tid == 1023) d_rowptr[NN] = sm[1023];
}

__global__ void k_fill(const void* __restrict__ ei) {
    int e = blockIdx.x * blockDim.x + threadIdx.x;
    if (e < EE) {
        int dst = edge_at(ei, d_is64, (size_t)EE + e);
        int src = edge_at(ei, d_is64, (size_t)e);
        int pos = atomicAdd(&d_cursor[dst], 1);
        if (pos >= 0 && pos < EE) d_colsrc[pos] = src;
    }
}

// ---------------- warp reduce helper ----------------
__device__ __forceinline__ float warp_sum(float v) {
#pragma unroll
    for (int off = 16; off; off >>= 1) v += __shfl_xor_sync(0xffffffffu, v, off);
    return v;
}

// ---------------- LN + message precompute ----------------
// g = relu(LN(h)); m = g + 1e-7; p = exp(t*m); q = m*p
__global__ void k_ln_msg(const float* __restrict__ gamma, const float* __restrict__ beta,
                         const float* __restrict__ tptr, int li) {
    int warp = (blockIdx.x * blockDim.x + threadIdx.x) >> 5;
    if (warp >= NN) return;
    int lane = threadIdx.x & 31;
    const float4 hv = *reinterpret_cast<const float4*>(&d_h[(size_t)warp * DD + lane * 4]);
    float s = hv.x + hv.y + hv.z + hv.w;
    s = warp_sum(s);
    float mu = s * (1.0f / DD);
    float dx = hv.x - mu, dy = hv.y - mu, dz = hv.z - mu, dw = hv.w - mu;
    float ss = dx * dx + dy * dy + dz * dz + dw * dw;
    ss = warp_sum(ss);
    float inv = rsqrtf(ss * (1.0f / DD) + 1e-5f);
    float tval = tptr[li];
    float4 gm = *reinterpret_cast<const float4*>(&gamma[lane * 4]);
    float4 bt = *reinterpret_cast<const float4*>(&beta[lane * 4]);
    float g0 = fmaxf(dx * inv * gm.x + bt.x, 0.0f);
    float g1 = fmaxf(dy * inv * gm.y + bt.y, 0.0f);
    float g2 = fmaxf(dz * inv * gm.z + bt.z, 0.0f);
    float g3 = fmaxf(dw * inv * gm.w + bt.w, 0.0f);
    float m0 = g0 + 1e-7f, m1 = g1 + 1e-7f, m2 = g2 + 1e-7f, m3 = g3 + 1e-7f;
    float4 p4 = make_float4(__expf(tval * m0), __expf(tval * m1),
                            __expf(tval * m2), __expf(tval * m3));
    float4 q4 = make_float4(m0 * p4.x, m1 * p4.y, m2 * p4.z, m3 * p4.w);
    *reinterpret_cast<float4*>(&d_g[(size_t)warp * DD + lane * 4]) = make_float4(g0, g1, g2, g3);
    *reinterpret_cast<float4*>(&d_pq[(size_t)warp * 2 * DD + lane * 4]) = p4;
    *reinterpret_cast<float4*>(&d_pq[(size_t)warp * 2 * DD + DD + lane * 4]) = q4;
}

// ---------------- CSR gather aggregation: no = g + (sum q)/(sum p + tiny) ----------------
__global__ void k_agg() {
    int n = (blockIdx.x * blockDim.x + threadIdx.x) >> 5;
    if (n >= NN) return;
    int lane = threadIdx.x & 31;
    int beg = d_rowptr[n], end = d_rowptr[n + 1];
    float4 den = make_float4(0.f, 0.f, 0.f, 0.f);
    float4 num = make_float4(0.f, 0.f, 0.f, 0.f);
    for (int e = beg; e < end; e++) {
        int s = d_colsrc[e];
        const float* base = &d_pq[(size_t)s * 2 * DD + lane * 4];
        float4 pv = *reinterpret_cast<const float4*>(base);
        float4 qv = *reinterpret_cast<const float4*>(base + DD);
        den.x += pv.x; den.y += pv.y; den.z += pv.z; den.w += pv.w;
        num.x += qv.x; num.y += qv.y; num.z += qv.z; num.w += qv.w;
    }
    float4 gv = *reinterpret_cast<const float4*>(&d_g[(size_t)n * DD + lane * 4]);
    float4 o;
    o.x = gv.x + num.x / (den.x + 1e-16f);
    o.y = gv.y + num.y / (den.y + 1e-16f);
    o.z = gv.z + num.z / (den.z + 1e-16f);
    o.w = gv.w + num.w / (den.w + 1e-16f);
    *reinterpret_cast<float4*>(&d_no[(size_t)n * DD + lane * 4]) = o;
}

// ---------------- LN over H=256 + relu (in-place on d_z) ----------------
__global__ void k_mln(const float* __restrict__ gamma, const float* __restrict__ beta) {
    int n = (blockIdx.x * blockDim.x + threadIdx.x) >> 5;
    if (n >= NN) return;
    int lane = threadIdx.x & 31;
    float* row = &d_z[(size_t)n * HH];
    float4 a = *reinterpret_cast<const float4*>(&row[lane * 4]);
    float4 b = *reinterpret_cast<const float4*>(&row[DD + lane * 4]);
    float s = a.x + a.y + a.z + a.w + b.x + b.y + b.z + b.w;
    s = warp_sum(s);
    float mu = s * (1.0f / HH);
    float ax = a.x - mu, ay = a.y - mu, az = a.z - mu, aw = a.w - mu;
    float bx = b.x - mu, by = b.y - mu, bz = b.z - mu, bw = b.w - mu;
    float ss = ax * ax + ay * ay + az * az + aw * aw + bx * bx + by * by + bz * bz + bw * bw;
    ss = warp_sum(ss);
    float inv = rsqrtf(ss * (1.0f / HH) + 1e-5f);
    float4 g1 = *reinterpret_cast<const float4*>(&gamma[lane * 4]);
    float4 g2 = *reinterpret_cast<const float4*>(&gamma[DD + lane * 4]);
    float4 c1 = *reinterpret_cast<const float4*>(&beta[lane * 4]);
    float4 c2 = *reinterpret_cast<const float4*>(&beta[DD + lane * 4]);
    float4 o1, o2;
    o1.x = fmaxf(ax * inv * g1.x + c1.x, 0.f);
    o1.y = fmaxf(ay * inv * g1.y + c1.y, 0.f);
    o1.z = fmaxf(az * inv * g1.z + c1.z, 0.f);
    o1.w = fmaxf(aw * inv * g1.w + c1.w, 0.f);
    o2.x = fmaxf(bx * inv * g2.x + c2.x, 0.f);
    o2.y = fmaxf(by * inv * g2.y + c2.y, 0.f);
    o2.z = fmaxf(bz * inv * g2.z + c2.z, 0.f);
    o2.w = fmaxf(bw * inv * g2.w + c2.w, 0.f);
    *reinterpret_cast<float4*>(&row[lane * 4]) = o1;
    *reinterpret_cast<float4*>(&row[DD + lane * 4]) = o2;
}

// ---------------- tiled SGEMM: C[M,N] = A[M,K] @ B[K,N] + bias (+epilogue) ----------------
// EPI: 0 = bias only, 1 = bias+relu, 2 = bias + residual add from d_h
#define BM 64
#define BN 64
#define BK 16
template <int EPI>
__global__ void sgemm(const float* Ap, int Aid, const float* __restrict__ B,
                      const float* __restrict__ bias, float* Cp, int Cid,
                      int M, int N, int K) {
    const float* __restrict__ A = resolve_c(Ap, Aid);
    float* __restrict__ C = resolve_m(Cp, Cid);
    __shared__ float As[BK][BM + 4];
    __shared__ float Bs[BK][BN];
    int t = threadIdx.x;
    int tx = t & 15, ty = t >> 4;
    int row0 = blockIdx.y * BM, col0 = blockIdx.x * BN;
    int ai = t >> 2, aj = (t & 3) * 4;   // A tile load: row ai, k-offset aj
    int bk = t >> 4, bn = (t & 15) * 4;  // B tile load: k bk, col bn
    float acc[4][4];
#pragma unroll
    for (int i = 0; i < 4; i++)
#pragma unroll
        for (int j = 0; j < 4; j++) acc[i][j] = 0.f;

    for (int k0 = 0; k0 < K; k0 += BK) {
        float4 a4;
        if (row0 + ai < M)
            a4 = *reinterpret_cast<const float4*>(&A[(size_t)(row0 + ai) * K + k0 + aj]);
        else
            a4 = make_float4(0.f, 0.f, 0.f, 0.f);
        As[aj + 0][ai] = a4.x;
        As[aj + 1][ai] = a4.y;
        As[aj + 2][ai] = a4.z;
        As[aj + 3][ai] = a4.w;
        float4 b4 = *reinterpret_cast<const float4*>(&B[(size_t)(k0 + bk) * N + col0 + bn]);
        *reinterpret_cast<float4*>(&Bs[bk][bn]) = b4;
        __syncthreads();
#pragma unroll
        for (int kk = 0; kk < BK; kk++) {
            float4 av = *reinterpret_cast<const float4*>(&As[kk][ty * 4]);
            float4 bv = *reinterpret_cast<const float4*>(&Bs[kk][tx * 4]);
            acc[0][0] += av.x * bv.x; acc[0][1] += av.x * bv.y; acc[0][2] += av.x * bv.z; acc[0][3] += av.x * bv.w;
            acc[1][0] += av.y * bv.x; acc[1][1] += av.y * bv.y; acc[1][2] += av.y * bv.z; acc[1][3] += av.y * bv.w;
            acc[2][0] += av.z * bv.x; acc[2][1] += av.z * bv.y; acc[2][2] += av.z * bv.z; acc[2][3] += av.z * bv.w;
            acc[3][0] += av.w * bv.x; acc[3][1] += av.w * bv.y; acc[3][2] += av.w * bv.z; acc[3][3] += av.w * bv.w;
        }
        __syncthreads();
    }
#pragma unroll
    for (int i = 0; i < 4; i++) {
        int r = row0 + ty * 4 + i;
        if (r < M) {
#pragma unroll
            for (int j = 0; j < 4; j++) {
                int c = col0 + tx * 4 + j;
                float v = acc[i][j] + bias[c];
                if (EPI == 1) v = fmaxf(v, 0.f);
                if (EPI == 2) v += d_h[(size_t)r * N + c];
                C[(size_t)r * N + c] = v;
            }
        }
    }
}

// ---------------- head: out[n, 0..1] = d_g[n] @ lin_W2 + lin_b2 ----------------
__global__ void k_head(const float* __restrict__ W, const float* __restrict__ b,
                       float* __restrict__ out) {
    int n = (blockIdx.x * blockDim.x + threadIdx.x) >> 5;
    if (n >= NN) return;
    int lane = threadIdx.x & 31;
    float4 v = *reinterpret_cast<const float4*>(&d_g[(size_t)n * DD + lane * 4]);
    float a0 = 0.f, a1 = 0.f;
    int d = lane * 4;
    a0 += v.x * W[(d + 0) * 2 + 0]; a1 += v.x * W[(d + 0) * 2 + 1];
    a0 += v.y * W[(d + 1) * 2 + 0]; a1 += v.y * W[(d + 1) * 2 + 1];
    a0 += v.z * W[(d + 2) * 2 + 0]; a1 += v.z * W[(d + 2) * 2 + 1];
    a0 += v.w * W[(d + 3) * 2 + 0]; a1 += v.w * W[(d + 3) * 2 + 1];
    a0 = warp_sum(a0);
    a1 = warp_sum(a1);
    if (lane == 0) {
        out[n * 2 + 0] = a0 + b[0];
        out[n * 2 + 1] = a1 + b[1];
    }
}

// ---------------- launch ----------------
extern "C" void kernel_launch(void* const* d_in, const int* in_sizes, int n_in,
                              void* d_out, int out_size) {
    const float* x     = (const float*)d_in[0];
    const void*  ei    = d_in[1];  // int32 or int64, probed at runtime
    const float* enc_W = (const float*)d_in[2];
    const float* enc_b = (const float*)d_in[3];
    const float* ln_g  = (const float*)d_in[4];
    const float* ln_b  = (const float*)d_in[5];
    const float* tt    = (const float*)d_in[6];
    const float* W1    = (const float*)d_in[7];
    const float* b1    = (const float*)d_in[8];
    const float* mg    = (const float*)d_in[9];
    const float* mb    = (const float*)d_in[10];
    const float* W2    = (const float*)d_in[11];
    const float* b2    = (const float*)d_in[12];
    const float* lW1   = (const float*)d_in[13];
    const float* lb1   = (const float*)d_in[14];
    const float* lW2   = (const float*)d_in[15];
    const float* lb2   = (const float*)d_in[16];
    float* out = (float*)d_out;

    // CSR build (dtype probe first)
    k_probe<<<1, 256>>>(ei);
    k_zero_deg<<<(NN + 255) / 256, 256>>>();
    k_count<<<(EE + 255) / 256, 256>>>(ei);
    k_scan<<<1, 1024>>>();
    k_fill<<<(EE + 255) / 256, 256>>>(ei);

    const int NWBLK = (NN * 32 + 255) / 256;  // warp-per-node kernels
    dim3 g128(DD / BN, (NN + BM - 1) / BM);
    dim3 g256(HH / BN, (NN + BM - 1) / BM);

    // encoder: d_h = x @ enc_W + enc_b
    sgemm<0><<<g128, 256>>>(x, 0, enc_W, enc_b, nullptr, 1, NN, DD, DD);

    for (int i = 0; i < LL; i++) {
        k_ln_msg<<<NWBLK, 256>>>(ln_g + i * DD, ln_b + i * DD, tt, i);
        k_agg<<<NWBLK, 256>>>();
        // d_z = d_no @ W1[i] + b1[i]
        sgemm<0><<<g256, 256>>>(nullptr, 3, W1 + (size_t)i * DD * HH, b1 + i * HH,
                                nullptr, 4, NN, HH, DD);
        k_mln<<<NWBLK, 256>>>(mg + i * HH, mb + i * HH);
        // d_h = d_z @ W2[i] + b2[i] + d_h   (residual)
        sgemm<2><<<g128, 256>>>(nullptr, 4, W2 + (size_t)i * HH * DD, b2 + i * DD,
                                nullptr, 1, NN, DD, HH);
    }

    // head: d_g = relu(d_h @ lin_W1 + lin_b1); out = d_g @ lin_W2 + lin_b2
    sgemm<1><<<g128, 256>>>(nullptr, 1, lW1, lb1, nullptr, 2, NN, DD, DD);
    k_head<<<NWBLK, 256>>>(lW2, lb2, out);
}

// round 5
// speedup vs baseline: 1.1864x; 1.1864x over previous
#include <cuda_runtime.h>
#include <cuda_bf16.h>
#include <mma.h>
#include <cstdint>

using namespace nvcuda;

// ---------------- problem constants (fixed shapes) ----------------
#define NN 50000
#define EE 600000
#define DD 128
#define HH 256
#define LL 6
#define SCB 256
#define NSCB ((NN + SCB - 1) / SCB)   // 196

// ---------------- device scratch (no allocs allowed) ----------------
__device__ __align__(128) float d_h [NN * DD];      // node features
__device__ __align__(128) float d_g [NN * DD];      // relu(LN(h)); head buf
__device__ __align__(128) float d_pq[NN * 2 * DD];  // [p | q] per node
__device__ __align__(128) float d_no[NN * DD];      // agg + g (pre-MLP)
__device__ __align__(128) float d_z [NN * HH];      // MLP hidden
__device__ int d_deg[NN];
__device__ int d_rowptr[NN + 1];
__device__ int d_cursor[NN];
__device__ int d_colsrc[EE];
__device__ int d_blksum[NSCB];
__device__ int d_is64;

// transposed + 2-term-bf16-split weights: Wt[n][k]
// layout: enc(128x128)@0 | W1[i](256x128) | W2[i](128x256) | lin(128x128)
#define WT_TOTAL 425984
__device__ __align__(16) __nv_bfloat16 d_wtb[WT_TOTAL];
__device__ __align__(16) __nv_bfloat16 d_wts[WT_TOTAL];

// Buffer ids: 0 = passed pointer, 1 = d_h, 2 = d_g, 3 = d_no, 4 = d_z
__device__ __forceinline__ const float* resolve_c(const float* p, int id) {
    switch (id) { case 1: return d_h; case 2: return d_g; case 3: return d_no; case 4: return d_z; default: return p; }
}
__device__ __forceinline__ float* resolve_m(float* p, int id) {
    switch (id) { case 1: return d_h; case 2: return d_g; case 3: return d_no; case 4: return d_z; default: return p; }
}

// ---------------- edge index decode (dtype-agnostic) ----------------
__device__ __forceinline__ int edge_at(const void* ei, int is64, size_t pos) {
    int v;
    if (is64) v = (int)((const long long*)ei)[pos];
    else      v = ((const int*)ei)[pos];
    if (v < 0) v = 0;
    if (v >= NN) v = NN - 1;
    return v;
}

__global__ void k_probe(const void* ei) {
    __shared__ int bad;
    if (threadIdx.x == 0) bad = 0;
    __syncthreads();
    const long long* p = (const long long*)ei;
    for (int i = threadIdx.x; i < 1024; i += blockDim.x) {
        long long v = p[i];
        if (v < 0 || v >= NN) bad = 1;
    }
    __syncthreads();
    if (threadIdx.x == 0) d_is64 = bad ? 0 : 1;
}

// ---------------- CSR build ----------------
__global__ void k_zero_deg() {
    int i = blockIdx.x * blockDim.x + threadIdx.x;
    if (i < NN) d_deg[i] = 0;
}
__global__ void k_count(const void* __restrict__ ei) {
    int e = blockIdx.x * blockDim.x + threadIdx.x;
    if (e < EE) atomicAdd(&d_deg[edge_at(ei, d_is64, (size_t)EE + e)], 1);
}
__global__ void k_scan1() {
    __shared__ int sm[SCB];
    int t = threadIdx.x;
    int i = blockIdx.x * SCB + t;
    sm[t] = (i < NN) ? d_deg[i] : 0;
    __syncthreads();
#pragma unroll
    for (int off = SCB / 2; off; off >>= 1) {
        if (t < off) sm[t] += sm[t + off];
        __syncthreads();
    }
    if (t == 0) d_blksum[blockIdx.x] = sm[0];
}
__global__ void k_scan2() {
    __shared__ int sm[SCB];
    int t = threadIdx.x;
    int v = (t < NSCB) ? d_blksum[t] : 0;
    sm[t] = v;
    __syncthreads();
#pragma unroll
    for (int off = 1; off < SCB; off <<= 1) {
        int u = (t >= off) ? sm[t - off] : 0;
        __syncthreads();
        sm[t] += u;
        __syncthreads();
    }
    if (t < NSCB) d_blksum[t] = sm[t] - v;  // exclusive
    if (t == SCB - 1) d_rowptr[NN] = sm[SCB - 1];
}
__global__ void k_scan3() {
    __shared__ int sm[SCB];
    int t = threadIdx.x;
    int i = blockIdx.x * SCB + t;
    int v = (i < NN) ? d_deg[i] : 0;
    sm[t] = v;
    __syncthreads();
#pragma unroll
    for (int off = 1; off < SCB; off <<= 1) {
        int u = (t >= off) ? sm[t - off] : 0;
        __syncthreads();
        sm[t] += u;
        __syncthreads();
    }
    int excl = sm[t] - v + d_blksum[blockIdx.x];
    if (i < NN) { d_rowptr[i] = excl; d_cursor[i] = excl; }
}
__global__ void k_fill(const void* __restrict__ ei) {
    int e = blockIdx.x * blockDim.x + threadIdx.x;
    if (e < EE) {
        int dst = edge_at(ei, d_is64, (size_t)EE + e);
        int src = edge_at(ei, d_is64, (size_t)e);
        int pos = atomicAdd(&d_cursor[dst], 1);
        if (pos >= 0 && pos < EE) d_colsrc[pos] = src;
    }
}

// ---------------- weight transpose + bf16 split: Wt[n][k] = W[k][n] ----------------
__global__ void k_tsplit(const float* __restrict__ W, int K, int N, int off) {
    int idx = blockIdx.x * blockDim.x + threadIdx.x;
    if (idx >= N * K) return;
    int n = idx / K, k = idx - n * K;
    float v = W[(size_t)k * N + n];
    __nv_bfloat16 b = __float2bfloat16_rn(v);
    d_wtb[off + idx] = b;
    d_wts[off + idx] = __float2bfloat16_rn(v - __bfloat162float(b));
}

// ---------------- warp reduce helper ----------------
__device__ __forceinline__ float warp_sum(float v) {
#pragma unroll
    for (int off = 16; off; off >>= 1) v += __shfl_xor_sync(0xffffffffu, v, off);
    return v;
}

// ---------------- LN + message precompute ----------------
__global__ void k_ln_msg(const float* __restrict__ gamma, const float* __restrict__ beta,
                         const float* __restrict__ tptr, int li) {
    int warp = (blockIdx.x * blockDim.x + threadIdx.x) >> 5;
    if (warp >= NN) return;
    int lane = threadIdx.x & 31;
    const float4 hv = *reinterpret_cast<const float4*>(&d_h[(size_t)warp * DD + lane * 4]);
    float s = warp_sum(hv.x + hv.y + hv.z + hv.w);
    float mu = s * (1.0f / DD);
    float dx = hv.x - mu, dy = hv.y - mu, dz = hv.z - mu, dw = hv.w - mu;
    float ss = warp_sum(dx * dx + dy * dy + dz * dz + dw * dw);
    float inv = rsqrtf(ss * (1.0f / DD) + 1e-5f);
    float tval = tptr[li];
    float4 gm = *reinterpret_cast<const float4*>(&gamma[lane * 4]);
    float4 bt = *reinterpret_cast<const float4*>(&beta[lane * 4]);
    float g0 = fmaxf(dx * inv * gm.x + bt.x, 0.0f);
    float g1 = fmaxf(dy * inv * gm.y + bt.y, 0.0f);
    float g2 = fmaxf(dz * inv * gm.z + bt.z, 0.0f);
    float g3 = fmaxf(dw * inv * gm.w + bt.w, 0.0f);
    float m0 = g0 + 1e-7f, m1 = g1 + 1e-7f, m2 = g2 + 1e-7f, m3 = g3 + 1e-7f;
    float4 p4 = make_float4(__expf(tval * m0), __expf(tval * m1), __expf(tval * m2), __expf(tval * m3));
    float4 q4 = make_float4(m0 * p4.x, m1 * p4.y, m2 * p4.z, m3 * p4.w);
    *reinterpret_cast<float4*>(&d_g[(size_t)warp * DD + lane * 4]) = make_float4(g0, g1, g2, g3);
    *reinterpret_cast<float4*>(&d_pq[(size_t)warp * 2 * DD + lane * 4]) = p4;
    *reinterpret_cast<float4*>(&d_pq[(size_t)warp * 2 * DD + DD + lane * 4]) = q4;
}

// ---------------- CSR gather aggregation ----------------
__global__ void k_agg() {
    int n = (blockIdx.x * blockDim.x + threadIdx.x) >> 5;
    if (n >= NN) return;
    int lane = threadIdx.x & 31;
    int beg = d_rowptr[n], end = d_rowptr[n + 1];
    float4 den = make_float4(0.f, 0.f, 0.f, 0.f);
    float4 num = make_float4(0.f, 0.f, 0.f, 0.f);
    for (int e = beg; e < end; e++) {
        int s = d_colsrc[e];
        const float* base = &d_pq[(size_t)s * 2 * DD + lane * 4];
        float4 pv = *reinterpret_cast<const float4*>(base);
        float4 qv = *reinterpret_cast<const float4*>(base + DD);
        den.x += pv.x; den.y += pv.y; den.z += pv.z; den.w += pv.w;
        num.x += qv.x; num.y += qv.y; num.z += qv.z; num.w += qv.w;
    }
    float4 gv = *reinterpret_cast<const float4*>(&d_g[(size_t)n * DD + lane * 4]);
    float4 o;
    o.x = gv.x + num.x / (den.x + 1e-16f);
    o.y = gv.y + num.y / (den.y + 1e-16f);
    o.z = gv.z + num.z / (den.z + 1e-16f);
    o.w = gv.w + num.w / (den.w + 1e-16f);
    *reinterpret_cast<float4*>(&d_no[(size_t)n * DD + lane * 4]) = o;
}

// ---------------- LN over H=256 + relu (in-place on d_z) ----------------
__global__ void k_mln(const float* __restrict__ gamma, const float* __restrict__ beta) {
    int n = (blockIdx.x * blockDim.x + threadIdx.x) >> 5;
    if (n >= NN) return;
    int lane = threadIdx.x & 31;
    float* row = &d_z[(size_t)n * HH];
    float4 a = *reinterpret_cast<const float4*>(&row[lane * 4]);
    float4 b = *reinterpret_cast<const float4*>(&row[DD + lane * 4]);
    float s = warp_sum(a.x + a.y + a.z + a.w + b.x + b.y + b.z + b.w);
    float mu = s * (1.0f / HH);
    float ax = a.x - mu, ay = a.y - mu, az = a.z - mu, aw = a.w - mu;
    float bx = b.x - mu, by = b.y - mu, bz = b.z - mu, bw = b.w - mu;
    float ss = warp_sum(ax * ax + ay * ay + az * az + aw * aw + bx * bx + by * by + bz * bz + bw * bw);
    float inv = rsqrtf(ss * (1.0f / HH) + 1e-5f);
    float4 g1 = *reinterpret_cast<const float4*>(&gamma[lane * 4]);
    float4 g2 = *reinterpret_cast<const float4*>(&gamma[DD + lane * 4]);
    float4 c1 = *reinterpret_cast<const float4*>(&beta[lane * 4]);
    float4 c2 = *reinterpret_cast<const float4*>(&beta[DD + lane * 4]);
    float4 o1, o2;
    o1.x = fmaxf(ax * inv * g1.x + c1.x, 0.f);
    o1.y = fmaxf(ay * inv * g1.y + c1.y, 0.f);
    o1.z = fmaxf(az * inv * g1.z + c1.z, 0.f);
    o1.w = fmaxf(aw * inv * g1.w + c1.w, 0.f);
    o2.x = fmaxf(bx * inv * g2.x + c2.x, 0.f);
    o2.y = fmaxf(by * inv * g2.y + c2.y, 0.f);
    o2.z = fmaxf(bz * inv * g2.z + c2.z, 0.f);
    o2.w = fmaxf(bw * inv * g2.w + c2.w, 0.f);
    *reinterpret_cast<float4*>(&row[lane * 4]) = o1;
    *reinterpret_cast<float4*>(&row[DD + lane * 4]) = o2;
}

// ---------------- WMMA GEMM (bf16 two-term split, fp32 accum) ----------------
// Block computes 128x128 output tile. grid = (ceil(M/128), TN/128).
// A [M, TK] fp32 row-major, split on-the-fly. B = pre-split Wt[n][k] bf16.
// D = A1B1 + A1B2 + A2B1. EPI: 0 bias, 1 bias+relu, 2 bias + residual(d_h).
#define ALD 136   // smem bf16 leading dim (8-elem pad)
#define CLD 132   // smem fp32 leading dim (4-elem pad)
template <int TN, int TK, int EPI>
__global__ void __launch_bounds__(256, 1) mm_gemm(const float* Ap, int Aid, int wtoff,
                                                  const float* __restrict__ bias,
                                                  float* Cp, int Cid) {
    extern __shared__ char smem[];
    __nv_bfloat16* SA1 = (__nv_bfloat16*)smem;
    __nv_bfloat16* SA2 = SA1 + 128 * ALD;
    __nv_bfloat16* SB1 = SA2 + 128 * ALD;
    __nv_bfloat16* SB2 = SB1 + 128 * ALD;
    float* SC = (float*)smem;

    const int tid = threadIdx.x;
    const int w = tid >> 5;
    const int rg = w >> 1;   // row group: 32 rows each
    const int cg = w & 1;    // col group: 64 cols each
    const int m0 = blockIdx.x * 128;
    const int n0 = blockIdx.y * 128;

    const float* __restrict__ A = resolve_c(Ap, Aid);
    float* __restrict__ C = resolve_m(Cp, Cid);

    wmma::fragment<wmma::accumulator, 16, 16, 16, float> acc[2][4];
#pragma unroll
    for (int i = 0; i < 2; i++)
#pragma unroll
        for (int j = 0; j < 4; j++) wmma::fill_fragment(acc[i][j], 0.0f);

    constexpr int CHUNKS = TK / 128;
    for (int kc = 0; kc < CHUNKS; kc++) {
        __syncthreads();
        // ---- A chunk: 128 rows x 128 k, fp32 -> split bf16 ----
        for (int idx = tid; idx < 128 * 32; idx += 256) {
            int row = idx >> 5, seg = idx & 31;  // kcol = seg*4
            float4 v = make_float4(0.f, 0.f, 0.f, 0.f);
            if (m0 + row < NN)
                v = *reinterpret_cast<const float4*>(&A[(size_t)(m0 + row) * TK + kc * 128 + seg * 4]);
            __nv_bfloat16 h0 = __float2bfloat16_rn(v.x), h1 = __float2bfloat16_rn(v.y);
            __nv_bfloat16 h2 = __float2bfloat16_rn(v.z), h3 = __float2bfloat16_rn(v.w);
            __nv_bfloat16 s0 = __float2bfloat16_rn(v.x - __bfloat162float(h0));
            __nv_bfloat16 s1 = __float2bfloat16_rn(v.y - __bfloat162float(h1));
            __nv_bfloat16 s2 = __float2bfloat16_rn(v.z - __bfloat162float(h2));
            __nv_bfloat16 s3 = __float2bfloat16_rn(v.w - __bfloat162float(h3));
            __nv_bfloat162 b01, b23, t01, t23;
            b01.x = h0; b01.y = h1; b23.x = h2; b23.y = h3;
            t01.x = s0; t01.y = s1; t23.x = s2; t23.y = s3;
            int o = row * ALD + seg * 4;
            *reinterpret_cast<uint2*>(&SA1[o]) =
                make_uint2(*reinterpret_cast<uint32_t*>(&b01), *reinterpret_cast<uint32_t*>(&b23));
            *reinterpret_cast<uint2*>(&SA2[o]) =
                make_uint2(*reinterpret_cast<uint32_t*>(&t01), *reinterpret_cast<uint32_t*>(&t23));
        }
        // ---- B chunk: 128 n-rows x 128 k (pre-split bf16) ----
        for (int idx = tid; idx < 128 * 16; idx += 256) {
            int row = idx >> 4, seg = idx & 15;  // kcol = seg*8
            size_t src = (size_t)wtoff + (size_t)(n0 + row) * TK + kc * 128 + seg * 8;
            int o = row * ALD + seg * 8;
            *reinterpret_cast<uint4*>(&SB1[o]) = *reinterpret_cast<const uint4*>(&d_wtb[src]);
            *reinterpret_cast<uint4*>(&SB2[o]) = *reinterpret_cast<const uint4*>(&d_wts[src]);
        }
        __syncthreads();
#pragma unroll
        for (int ks = 0; ks < 8; ks++) {
            wmma::fragment<wmma::matrix_a, 16, 16, 16, __nv_bfloat16, wmma::row_major> a1[2], a2[2];
            wmma::fragment<wmma::matrix_b, 16, 16, 16, __nv_bfloat16, wmma::col_major> b1[4], b2[4];
#pragma unroll
            for (int i = 0; i < 2; i++) {
                wmma::load_matrix_sync(a1[i], &SA1[(rg * 32 + i * 16) * ALD + ks * 16], ALD);
                wmma::load_matrix_sync(a2[i], &SA2[(rg * 32 + i * 16) * ALD + ks * 16], ALD);
            }
#pragma unroll
            for (int j = 0; j < 4; j++) {
                wmma::load_matrix_sync(b1[j], &SB1[(cg * 64 + j * 16) * ALD + ks * 16], ALD);
                wmma::load_matrix_sync(b2[j], &SB2[(cg * 64 + j * 16) * ALD + ks * 16], ALD);
            }
#pragma unroll
            for (int i = 0; i < 2; i++)
#pragma unroll
                for (int j = 0; j < 4; j++) {
                    wmma::mma_sync(acc[i][j], a1[i], b1[j], acc[i][j]);
                    wmma::mma_sync(acc[i][j], a1[i], b2[j], acc[i][j]);
                    wmma::mma_sync(acc[i][j], a2[i], b1[j], acc[i][j]);
                }
        }
    }
    __syncthreads();
#pragma unroll
    for (int i = 0; i < 2; i++)
#pragma unroll
        for (int j = 0; j < 4; j++)
            wmma::store_matrix_sync(&SC[(rg * 32 + i * 16) * CLD + cg * 64 + j * 16],
                                    acc[i][j], CLD, wmma::mem_row_major);
    __syncthreads();
    // ---- epilogue ----
    for (int idx = tid; idx < 128 * 32; idx += 256) {
        int row = idx >> 5, seg = idx & 31;
        int r = m0 + row;
        if (r >= NN) continue;
        float4 v = *reinterpret_cast<const float4*>(&SC[row * CLD + seg * 4]);
        int col = n0 + seg * 4;
        v.x += bias[col + 0]; v.y += bias[col + 1];
        v.z += bias[col + 2]; v.w += bias[col + 3];
        if (EPI == 1) {
            v.x = fmaxf(v.x, 0.f); v.y = fmaxf(v.y, 0.f);
            v.z = fmaxf(v.z, 0.f); v.w = fmaxf(v.w, 0.f);
        }
        if (EPI == 2) {
            const float4 h4 = *reinterpret_cast<const float4*>(&d_h[(size_t)r * TN + col]);
            v.x += h4.x; v.y += h4.y; v.z += h4.z; v.w += h4.w;
        }
        *reinterpret_cast<float4*>(&C[(size_t)r * TN + col]) = v;
    }
}

// ---------------- head: out[n, 0..1] = d_g[n] @ lin_W2 + lin_b2 ----------------
__global__ void k_head(const float* __restrict__ W, const float* __restrict__ b,
                       float* __restrict__ out) {
    int n = (blockIdx.x * blockDim.x + threadIdx.x) >> 5;
    if (n >= NN) return;
    int lane = threadIdx.x & 31;
    float4 v = *reinterpret_cast<const float4*>(&d_g[(size_t)n * DD + lane * 4]);
    float a0 = 0.f, a1 = 0.f;
    int d = lane * 4;
    a0 += v.x * W[(d + 0) * 2 + 0]; a1 += v.x * W[(d + 0) * 2 + 1];
    a0 += v.y * W[(d + 1) * 2 + 0]; a1 += v.y * W[(d + 1) * 2 + 1];
    a0 += v.z * W[(d + 2) * 2 + 0]; a1 += v.z * W[(d + 2) * 2 + 1];
    a0 += v.w * W[(d + 3) * 2 + 0]; a1 += v.w * W[(d + 3) * 2 + 1];
    a0 = warp_sum(a0);
    a1 = warp_sum(a1);
    if (lane == 0) {
        out[n * 2 + 0] = a0 + b[0];
        out[n * 2 + 1] = a1 + b[1];
    }
}

// ---------------- launch ----------------
#define OFF_ENC 0
#define OFF_W1(i) (16384 + (i) * 32768)
#define OFF_W2(i) (16384 + 6 * 32768 + (i) * 32768)
#define OFF_LIN (16384 + 12 * 32768)

extern "C" void kernel_launch(void* const* d_in, const int* in_sizes, int n_in,
                              void* d_out, int out_size) {
    const float* x     = (const float*)d_in[0];
    const void*  ei    = d_in[1];
    const float* enc_W = (const float*)d_in[2];
    const float* enc_b = (const float*)d_in[3];
    const float* ln_g  = (const float*)d_in[4];
    const float* ln_b  = (const float*)d_in[5];
    const float* tt    = (const float*)d_in[6];
    const float* W1    = (const float*)d_in[7];
    const float* b1    = (const float*)d_in[8];
    const float* mg    = (const float*)d_in[9];
    const float* mb    = (const float*)d_in[10];
    const float* W2    = (const float*)d_in[11];
    const float* b2    = (const float*)d_in[12];
    const float* lW1   = (const float*)d_in[13];
    const float* lb1   = (const float*)d_in[14];
    const float* lW2   = (const float*)d_in[15];
    const float* lb2   = (const float*)d_in[16];
    float* out = (float*)d_out;

    const int SMEM = 4 * 128 * ALD * 2;  // 139264 bytes
    cudaFuncSetAttribute(mm_gemm<128, 128, 0>, cudaFuncAttributeMaxDynamicSharedMemorySize, SMEM);
    cudaFuncSetAttribute(mm_gemm<256, 128, 0>, cudaFuncAttributeMaxDynamicSharedMemorySize, SMEM);
    cudaFuncSetAttribute(mm_gemm<128, 256, 2>, cudaFuncAttributeMaxDynamicSharedMemorySize, SMEM);
    cudaFuncSetAttribute(mm_gemm<128, 128, 1>, cudaFuncAttributeMaxDynamicSharedMemorySize, SMEM);

    // weight prep (transpose + split)
    k_tsplit<<<(128 * 128 + 255) / 256, 256>>>(enc_W, 128, 128, OFF_ENC);
    for (int i = 0; i < LL; i++) {
        k_tsplit<<<(128 * 256 + 255) / 256, 256>>>(W1 + (size_t)i * DD * HH, 128, 256, OFF_W1(i));
        k_tsplit<<<(256 * 128 + 255) / 256, 256>>>(W2 + (size_t)i * HH * DD, 256, 128, OFF_W2(i));
    }
    k_tsplit<<<(128 * 128 + 255) / 256, 256>>>(lW1, 128, 128, OFF_LIN);

    // CSR build
    k_probe<<<1, 256>>>(ei);
    k_zero_deg<<<(NN + 255) / 256, 256>>>();
    k_count<<<(EE + 255) / 256, 256>>>(ei);
    k_scan1<<<NSCB, SCB>>>();
    k_scan2<<<1, SCB>>>();
    k_scan3<<<NSCB, SCB>>>();
    k_fill<<<(EE + 255) / 256, 256>>>(ei);

    const int NWBLK = (NN * 32 + 255) / 256;
    const int MBLK = (NN + 127) / 128;  // 391

    // encoder: d_h = x @ enc_W + enc_b
    mm_gemm<128, 128, 0><<<dim3(MBLK, 1), 256, SMEM>>>(x, 0, OFF_ENC, enc_b, nullptr, 1);

    for (int i = 0; i < LL; i++) {
        k_ln_msg<<<NWBLK, 256>>>(ln_g + i * DD, ln_b + i * DD, tt, i);
        k_agg<<<NWBLK, 256>>>();
        // d_z = d_no @ W1[i] + b1[i]   (N=256 -> grid.y = 2)
        mm_gemm<256, 128, 0><<<dim3(MBLK, 2), 256, SMEM>>>(nullptr, 3, OFF_W1(i), b1 + i * HH, nullptr, 4);
        k_mln<<<NWBLK, 256>>>(mg + i * HH, mb + i * HH);
        // d_h = d_z @ W2[i] + b2[i] + d_h
        mm_gemm<128, 256, 2><<<dim3(MBLK, 1), 256, SMEM>>>(nullptr, 4, OFF_W2(i), b2 + i * DD, nullptr, 1);
    }

    // head: d_g = relu(d_h @ lin_W1 + lin_b1); out = d_g @ lin_W2 + lin_b2
    mm_gemm<128, 128, 1><<<dim3(MBLK, 1), 256, SMEM>>>(nullptr, 1, OFF_LIN, lb1, nullptr, 2);
    k_head<<<NWBLK, 256>>>(lW2, lb2, out);
}

// round 6
// speedup vs baseline: 1.5141x; 1.2762x over previous
#include <cuda_runtime.h>
#include <cuda_bf16.h>
#include <cuda_fp16.h>
#include <mma.h>
#include <cstdint>

using namespace nvcuda;

// ---------------- problem constants (fixed shapes) ----------------
#define NN 50000
#define EE 600000
#define DD 128
#define HH 256
#define LL 6
#define SCB 256
#define NSCB ((NN + SCB - 1) / SCB)   // 196

// ---------------- device scratch (no allocs allowed) ----------------
__device__ __align__(128) float d_h [NN * DD];        // node features
__device__ __align__(128) float d_g [NN * DD];        // relu(LN(h)); head buf
__device__ __align__(128) __half2 d_pqh[NN * DD];     // (p, q) per node/dim, fp16
__device__ __align__(128) float d_no[NN * DD];        // agg + g (pre-MLP)
__device__ __align__(128) float d_z [NN * HH];        // MLP hidden
__device__ int d_deg[NN];
__device__ int d_rowptr[NN + 1];
__device__ int d_cursor[NN];
__device__ int d_colsrc[EE];
__device__ int d_blksum[NSCB];
__device__ int d_is64;

// transposed + 2-term-bf16-split weights: Wt[n][k]
// layout: enc(128x128)@0 | W1[i](256x128)@16384+i*32768 | W2[i](128x256)@212992+(i)*32768 | lin@409600
#define WT_TOTAL 425984
__device__ __align__(16) __nv_bfloat16 d_wtb[WT_TOTAL];
__device__ __align__(16) __nv_bfloat16 d_wts[WT_TOTAL];

// Buffer ids: 0 = passed pointer, 1 = d_h, 2 = d_g, 3 = d_no, 4 = d_z
__device__ __forceinline__ const float* resolve_c(const float* p, int id) {
    switch (id) { case 1: return d_h; case 2: return d_g; case 3: return d_no; case 4: return d_z; default: return p; }
}
__device__ __forceinline__ float* resolve_m(float* p, int id) {
    switch (id) { case 1: return d_h; case 2: return d_g; case 3: return d_no; case 4: return d_z; default: return p; }
}

// ---------------- edge index decode (dtype-agnostic) ----------------
__device__ __forceinline__ int edge_at(const void* ei, int is64, size_t pos) {
    int v;
    if (is64) v = (int)((const long long*)ei)[pos];
    else      v = ((const int*)ei)[pos];
    if (v < 0) v = 0;
    if (v >= NN) v = NN - 1;
    return v;
}

__global__ void k_probe(const void* ei) {
    __shared__ int bad;
    if (threadIdx.x == 0) bad = 0;
    __syncthreads();
    const long long* p = (const long long*)ei;
    for (int i = threadIdx.x; i < 1024; i += blockDim.x) {
        long long v = p[i];
        if (v < 0 || v >= NN) bad = 1;
    }
    __syncthreads();
    if (threadIdx.x == 0) d_is64 = bad ? 0 : 1;
}

// ---------------- CSR build ----------------
__global__ void k_zero_deg() {
    int i = blockIdx.x * blockDim.x + threadIdx.x;
    if (i < NN) d_deg[i] = 0;
}
__global__ void k_count(const void* __restrict__ ei) {
    int e = blockIdx.x * blockDim.x + threadIdx.x;
    if (e < EE) atomicAdd(&d_deg[edge_at(ei, d_is64, (size_t)EE + e)], 1);
}
__global__ void k_scan1() {
    __shared__ int sm[SCB];
    int t = threadIdx.x;
    int i = blockIdx.x * SCB + t;
    sm[t] = (i < NN) ? d_deg[i] : 0;
    __syncthreads();
#pragma unroll
    for (int off = SCB / 2; off; off >>= 1) {
        if (t < off) sm[t] += sm[t + off];
        __syncthreads();
    }
    if (t == 0) d_blksum[blockIdx.x] = sm[0];
}
__global__ void k_scan2() {
    __shared__ int sm[SCB];
    int t = threadIdx.x;
    int v = (t < NSCB) ? d_blksum[t] : 0;
    sm[t] = v;
    __syncthreads();
#pragma unroll
    for (int off = 1; off < SCB; off <<= 1) {
        int u = (t >= off) ? sm[t - off] : 0;
        __syncthreads();
        sm[t] += u;
        __syncthreads();
    }
    if (t < NSCB) d_blksum[t] = sm[t] - v;
    if (t == SCB - 1) d_rowptr[NN] = sm[SCB - 1];
}
__global__ void k_scan3() {
    __shared__ int sm[SCB];
    int t = threadIdx.x;
    int i = blockIdx.x * SCB + t;
    int v = (i < NN) ? d_deg[i] : 0;
    sm[t] = v;
    __syncthreads();
#pragma unroll
    for (int off = 1; off < SCB; off <<= 1) {
        int u = (t >= off) ? sm[t - off] : 0;
        __syncthreads();
        sm[t] += u;
        __syncthreads();
    }
    int excl = sm[t] - v + d_blksum[blockIdx.x];
    if (i < NN) { d_rowptr[i] = excl; d_cursor[i] = excl; }
}
__global__ void k_fill(const void* __restrict__ ei) {
    int e = blockIdx.x * blockDim.x + threadIdx.x;
    if (e < EE) {
        int dst = edge_at(ei, d_is64, (size_t)EE + e);
        int src = edge_at(ei, d_is64, (size_t)e);
        int pos = atomicAdd(&d_cursor[dst], 1);
        if (pos >= 0 && pos < EE) d_colsrc[pos] = src;
    }
}

// ---------------- merged weight transpose + bf16 split (one launch) ----------------
__global__ void k_tsplit_all(const float* __restrict__ encW, const float* __restrict__ W1,
                             const float* __restrict__ W2, const float* __restrict__ lW1) {
    int idx = blockIdx.x * blockDim.x + threadIdx.x;
    if (idx >= WT_TOTAL) return;
    float v;
    if (idx < 16384) {
        int n = idx >> 7, k = idx & 127;
        v = encW[k * 128 + n];
    } else if (idx < 409600) {
        int r = (idx - 16384) >> 15;
        int wi = (idx - 16384) & 32767;
        if (r < 6) {            // W1 layer r: [128 k][256 n] -> Wt[n(256)][k(128)]
            int n = wi >> 7, k = wi & 127;
            v = W1[(size_t)r * 32768 + k * 256 + n];
        } else {                // W2 layer r-6: [256 k][128 n] -> Wt[n(128)][k(256)]
            int n = wi >> 8, k = wi & 255;
            v = W2[(size_t)(r - 6) * 32768 + k * 128 + n];
        }
    } else {
        int wi = idx - 409600;
        int n = wi >> 7, k = wi & 127;
        v = lW1[k * 128 + n];
    }
    __nv_bfloat16 b = __float2bfloat16_rn(v);
    d_wtb[idx] = b;
    d_wts[idx] = __float2bfloat16_rn(v - __bfloat162float(b));
}

// ---------------- warp reduce helper ----------------
__device__ __forceinline__ float warp_sum(float v) {
#pragma unroll
    for (int off = 16; off; off >>= 1) v += __shfl_xor_sync(0xffffffffu, v, off);
    return v;
}

// ---------------- CSR gather aggregation (fp16 pq): no = g + (sum q)/(sum p) ----------------
__global__ void k_agg() {
    int n = (blockIdx.x * blockDim.x + threadIdx.x) >> 5;
    if (n >= NN) return;
    int lane = threadIdx.x & 31;
    int beg = d_rowptr[n], end = d_rowptr[n + 1];
    float4 den = make_float4(0.f, 0.f, 0.f, 0.f);
    float4 num = make_float4(0.f, 0.f, 0.f, 0.f);
    for (int e = beg; e < end; e++) {
        int s = d_colsrc[e];
        uint4 u = *reinterpret_cast<const uint4*>(&d_pqh[(size_t)s * DD + lane * 4]);
        float2 f0 = __half22float2(*reinterpret_cast<__half2*>(&u.x));
        float2 f1 = __half22float2(*reinterpret_cast<__half2*>(&u.y));
        float2 f2 = __half22float2(*reinterpret_cast<__half2*>(&u.z));
        float2 f3 = __half22float2(*reinterpret_cast<__half2*>(&u.w));
        den.x += f0.x; num.x += f0.y;
        den.y += f1.x; num.y += f1.y;
        den.z += f2.x; num.z += f2.y;
        den.w += f3.x; num.w += f3.y;
    }
    float4 gv = *reinterpret_cast<const float4*>(&d_g[(size_t)n * DD + lane * 4]);
    float4 o;
    o.x = gv.x + num.x / (den.x + 1e-16f);
    o.y = gv.y + num.y / (den.y + 1e-16f);
    o.z = gv.z + num.z / (den.z + 1e-16f);
    o.w = gv.w + num.w / (den.w + 1e-16f);
    *reinterpret_cast<float4*>(&d_no[(size_t)n * DD + lane * 4]) = o;
}

// ---------------- bf16 split helper ----------------
__device__ __forceinline__ void split4(float4 v, uint2& big, uint2& small) {
    __nv_bfloat16 h0 = __float2bfloat16_rn(v.x), h1 = __float2bfloat16_rn(v.y);
    __nv_bfloat16 h2 = __float2bfloat16_rn(v.z), h3 = __float2bfloat16_rn(v.w);
    __nv_bfloat16 s0 = __float2bfloat16_rn(v.x - __bfloat162float(h0));
    __nv_bfloat16 s1 = __float2bfloat16_rn(v.y - __bfloat162float(h1));
    __nv_bfloat16 s2 = __float2bfloat16_rn(v.z - __bfloat162float(h2));
    __nv_bfloat16 s3 = __float2bfloat16_rn(v.w - __bfloat162float(h3));
    __nv_bfloat162 b01, b23, t01, t23;
    b01.x = h0; b01.y = h1; b23.x = h2; b23.y = h3;
    t01.x = s0; t01.y = s1; t23.x = s2; t23.y = s3;
    big = make_uint2(*reinterpret_cast<uint32_t*>(&b01), *reinterpret_cast<uint32_t*>(&b23));
    small = make_uint2(*reinterpret_cast<uint32_t*>(&t01), *reinterpret_cast<uint32_t*>(&t23));
}

#define ALD 136   // smem bf16 leading dim
#define CLD 132   // smem fp32 leading dim (TN=128)
#define CLD2 260  // smem fp32 leading dim (TN=256)

// ---------------- GEMM (TN=128): C = A@W + bias [+resid] [+relu] [+msg epilogue] ----------------
// D = A1B1 + A1B2 + A2B1 (two-term bf16 split, err ~2^-16).
template <int TK, bool RESID, bool DO_MSG, bool RELU>
__global__ void __launch_bounds__(256, 1) gemm_std(const float* Ap, int Aid, int wtoff,
                                                   const float* __restrict__ bias,
                                                   float* Cp, int Cid,
                                                   const float* __restrict__ gamma,
                                                   const float* __restrict__ beta,
                                                   const float* __restrict__ tptr, int li) {
    extern __shared__ char smem[];
    __nv_bfloat16* SA1 = (__nv_bfloat16*)smem;
    __nv_bfloat16* SA2 = SA1 + 128 * ALD;
    __nv_bfloat16* SB1 = SA2 + 128 * ALD;
    __nv_bfloat16* SB2 = SB1 + 128 * ALD;
    float* SC = (float*)smem;

    const int tid = threadIdx.x;
    const int w = tid >> 5, lane = tid & 31;
    const int rg = w >> 1;   // 32-row group
    const int cg = w & 1;    // 64-col group
    const int m0 = blockIdx.x * 128;

    const float* __restrict__ A = resolve_c(Ap, Aid);
    float* __restrict__ C = resolve_m(Cp, Cid);

    wmma::fragment<wmma::accumulator, 16, 16, 16, float> acc[2][4];
#pragma unroll
    for (int i = 0; i < 2; i++)
#pragma unroll
        for (int j = 0; j < 4; j++) wmma::fill_fragment(acc[i][j], 0.0f);

    constexpr int CHUNKS = TK / 128;
    for (int kc = 0; kc < CHUNKS; kc++) {
        __syncthreads();
        for (int idx = tid; idx < 128 * 32; idx += 256) {
            int row = idx >> 5, seg = idx & 31;
            float4 v = make_float4(0.f, 0.f, 0.f, 0.f);
            if (m0 + row < NN)
                v = *reinterpret_cast<const float4*>(&A[(size_t)(m0 + row) * TK + kc * 128 + seg * 4]);
            uint2 big, sml;
            split4(v, big, sml);
            int o = row * ALD + seg * 4;
            *reinterpret_cast<uint2*>(&SA1[o]) = big;
            *reinterpret_cast<uint2*>(&SA2[o]) = sml;
        }
        for (int idx = tid; idx < 128 * 16; idx += 256) {
            int row = idx >> 4, seg = idx & 15;
            size_t src = (size_t)wtoff + (size_t)row * TK + kc * 128 + seg * 8;
            int o = row * ALD + seg * 8;
            *reinterpret_cast<uint4*>(&SB1[o]) = *reinterpret_cast<const uint4*>(&d_wtb[src]);
            *reinterpret_cast<uint4*>(&SB2[o]) = *reinterpret_cast<const uint4*>(&d_wts[src]);
        }
        __syncthreads();
#pragma unroll
        for (int ks = 0; ks < 8; ks++) {
            wmma::fragment<wmma::matrix_a, 16, 16, 16, __nv_bfloat16, wmma::row_major> a1[2], a2[2];
#pragma unroll
            for (int i = 0; i < 2; i++) {
                wmma::load_matrix_sync(a1[i], &SA1[(rg * 32 + i * 16) * ALD + ks * 16], ALD);
                wmma::load_matrix_sync(a2[i], &SA2[(rg * 32 + i * 16) * ALD + ks * 16], ALD);
            }
#pragma unroll
            for (int j = 0; j < 4; j++) {
                wmma::fragment<wmma::matrix_b, 16, 16, 16, __nv_bfloat16, wmma::col_major> b1, b2;
                wmma::load_matrix_sync(b1, &SB1[(cg * 64 + j * 16) * ALD + ks * 16], ALD);
                wmma::load_matrix_sync(b2, &SB2[(cg * 64 + j * 16) * ALD + ks * 16], ALD);
#pragma unroll
                for (int i = 0; i < 2; i++) {
                    wmma::mma_sync(acc[i][j], a1[i], b1, acc[i][j]);
                    wmma::mma_sync(acc[i][j], a1[i], b2, acc[i][j]);
                    wmma::mma_sync(acc[i][j], a2[i], b1, acc[i][j]);
                }
            }
        }
    }
    __syncthreads();
#pragma unroll
    for (int i = 0; i < 2; i++)
#pragma unroll
        for (int j = 0; j < 4; j++)
            wmma::store_matrix_sync(&SC[(rg * 32 + i * 16) * CLD + cg * 64 + j * 16],
                                    acc[i][j], CLD, wmma::mem_row_major);
    __syncthreads();

    // ---- fused epilogue: warp w owns rows w*16 .. w*16+15 ----
    const int col = lane * 4;
    float tval = 0.f;
    if (DO_MSG) tval = tptr[li];
    float4 bi = *reinterpret_cast<const float4*>(&bias[col]);
    float4 gm, bt;
    if (DO_MSG) {
        gm = *reinterpret_cast<const float4*>(&gamma[col]);
        bt = *reinterpret_cast<const float4*>(&beta[col]);
    }
#pragma unroll 1
    for (int rr = 0; rr < 16; rr++) {
        int row = w * 16 + rr;
        int r = m0 + row;
        if (r >= NN) continue;
        float4 v = *reinterpret_cast<const float4*>(&SC[row * CLD + col]);
        v.x += bi.x; v.y += bi.y; v.z += bi.z; v.w += bi.w;
        if (RESID) {
            float4 h4 = *reinterpret_cast<const float4*>(&d_h[(size_t)r * DD + col]);
            v.x += h4.x; v.y += h4.y; v.z += h4.z; v.w += h4.w;
        }
        if (RELU) {
            v.x = fmaxf(v.x, 0.f); v.y = fmaxf(v.y, 0.f);
            v.z = fmaxf(v.z, 0.f); v.w = fmaxf(v.w, 0.f);
        }
        *reinterpret_cast<float4*>(&C[(size_t)r * DD + col]) = v;
        if (DO_MSG) {
            float s = warp_sum(v.x + v.y + v.z + v.w);
            float mu = s * (1.0f / DD);
            float dx = v.x - mu, dy = v.y - mu, dz = v.z - mu, dw = v.w - mu;
            float ss = warp_sum(dx * dx + dy * dy + dz * dz + dw * dw);
            float inv = rsqrtf(ss * (1.0f / DD) + 1e-5f);
            float g0 = fmaxf(dx * inv * gm.x + bt.x, 0.0f);
            float g1 = fmaxf(dy * inv * gm.y + bt.y, 0.0f);
            float g2 = fmaxf(dz * inv * gm.z + bt.z, 0.0f);
            float g3 = fmaxf(dw * inv * gm.w + bt.w, 0.0f);
            *reinterpret_cast<float4*>(&d_g[(size_t)r * DD + col]) = make_float4(g0, g1, g2, g3);
            float m0f = g0 + 1e-7f, m1f = g1 + 1e-7f, m2f = g2 + 1e-7f, m3f = g3 + 1e-7f;
            float p0 = __expf(tval * m0f), p1 = __expf(tval * m1f);
            float p2 = __expf(tval * m2f), p3 = __expf(tval * m3f);
            __half2 pq0 = __floats2half2_rn(p0, m0f * p0);
            __half2 pq1 = __floats2half2_rn(p1, m1f * p1);
            __half2 pq2 = __floats2half2_rn(p2, m2f * p2);
            __half2 pq3 = __floats2half2_rn(p3, m3f * p3);
            uint4 u = make_uint4(*reinterpret_cast<uint32_t*>(&pq0), *reinterpret_cast<uint32_t*>(&pq1),
                                 *reinterpret_cast<uint32_t*>(&pq2), *reinterpret_cast<uint32_t*>(&pq3));
            *reinterpret_cast<uint4*>(&d_pqh[(size_t)r * DD + col]) = u;
        }
    }
}

// ---------------- GEMM1 (TN=256, TK=128) fused LN(256)+relu -> d_z ----------------
__global__ void __launch_bounds__(512, 1) gemm_mlp1(int wtoff, const float* __restrict__ bias,
                                                    const float* __restrict__ gamma,
                                                    const float* __restrict__ beta) {
    extern __shared__ char smem[];
    __nv_bfloat16* SA1 = (__nv_bfloat16*)smem;
    __nv_bfloat16* SA2 = SA1 + 128 * ALD;
    __nv_bfloat16* SB1 = SA2 + 128 * ALD;
    __nv_bfloat16* SB2 = SB1 + 256 * ALD;
    float* SC = (float*)smem;

    const int tid = threadIdx.x;
    const int w = tid >> 5, lane = tid & 31;
    const int rg = w >> 1;   // 0..7: 16-row group
    const int cg = w & 1;    // 0..1: 128-col group
    const int m0 = blockIdx.x * 128;

    wmma::fragment<wmma::accumulator, 16, 16, 16, float> acc[8];
#pragma unroll
    for (int j = 0; j < 8; j++) wmma::fill_fragment(acc[j], 0.0f);

    for (int idx = tid; idx < 128 * 32; idx += 512) {
        int row = idx >> 5, seg = idx & 31;
        float4 v = make_float4(0.f, 0.f, 0.f, 0.f);
        if (m0 + row < NN)
            v = *reinterpret_cast<const float4*>(&d_no[(size_t)(m0 + row) * DD + seg * 4]);
        uint2 big, sml;
        split4(v, big, sml);
        int o = row * ALD + seg * 4;
        *reinterpret_cast<uint2*>(&SA1[o]) = big;
        *reinterpret_cast<uint2*>(&SA2[o]) = sml;
    }
    for (int idx = tid; idx < 256 * 16; idx += 512) {
        int row = idx >> 4, seg = idx & 15;
        size_t src = (size_t)wtoff + (size_t)row * DD + seg * 8;
        int o = row * ALD + seg * 8;
        *reinterpret_cast<uint4*>(&SB1[o]) = *reinterpret_cast<const uint4*>(&d_wtb[src]);
        *reinterpret_cast<uint4*>(&SB2[o]) = *reinterpret_cast<const uint4*>(&d_wts[src]);
    }
    __syncthreads();
#pragma unroll
    for (int ks = 0; ks < 8; ks++) {
        wmma::fragment<wmma::matrix_a, 16, 16, 16, __nv_bfloat16, wmma::row_major> a1, a2;
        wmma::load_matrix_sync(a1, &SA1[(rg * 16) * ALD + ks * 16], ALD);
        wmma::load_matrix_sync(a2, &SA2[(rg * 16) * ALD + ks * 16], ALD);
#pragma unroll
        for (int j = 0; j < 8; j++) {
            wmma::fragment<wmma::matrix_b, 16, 16, 16, __nv_bfloat16, wmma::col_major> b1, b2;
            wmma::load_matrix_sync(b1, &SB1[(cg * 128 + j * 16) * ALD + ks * 16], ALD);
            wmma::load_matrix_sync(b2, &SB2[(cg * 128 + j * 16) * ALD + ks * 16], ALD);
            wmma::mma_sync(acc[j], a1, b1, acc[j]);
            wmma::mma_sync(acc[j], a1, b2, acc[j]);
            wmma::mma_sync(acc[j], a2, b1, acc[j]);
        }
    }
    __syncthreads();
#pragma unroll
    for (int j = 0; j < 8; j++)
        wmma::store_matrix_sync(&SC[(rg * 16) * CLD2 + cg * 128 + j * 16], acc[j], CLD2, wmma::mem_row_major);
    __syncthreads();

    // ---- fused LN(256)+relu epilogue: warp w owns rows w*8 .. w*8+7 ----
    const int c1 = lane * 4, c2 = DD + lane * 4;
    float4 bA = *reinterpret_cast<const float4*>(&bias[c1]);
    float4 bB = *reinterpret_cast<const float4*>(&bias[c2]);
    float4 g1 = *reinterpret_cast<const float4*>(&gamma[c1]);
    float4 g2 = *reinterpret_cast<const float4*>(&gamma[c2]);
    float4 t1 = *reinterpret_cast<const float4*>(&beta[c1]);
    float4 t2 = *reinterpret_cast<const float4*>(&beta[c2]);
#pragma unroll 1
    for (int rr = 0; rr < 8; rr++) {
        int row = w * 8 + rr;
        int r = m0 + row;
        if (r >= NN) continue;
        float4 a = *reinterpret_cast<const float4*>(&SC[row * CLD2 + c1]);
        float4 b = *reinterpret_cast<const float4*>(&SC[row * CLD2 + c2]);
        a.x += bA.x; a.y += bA.y; a.z += bA.z; a.w += bA.w;
        b.x += bB.x; b.y += bB.y; b.z += bB.z; b.w += bB.w;
        float s = warp_sum(a.x + a.y + a.z + a.w + b.x + b.y + b.z + b.w);
        float mu = s * (1.0f / HH);
        float ax = a.x - mu, ay = a.y - mu, az = a.z - mu, aw = a.w - mu;
        float bx = b.x - mu, by = b.y - mu, bz = b.z - mu, bw = b.w - mu;
        float ss = warp_sum(ax * ax + ay * ay + az * az + aw * aw + bx * bx + by * by + bz * bz + bw * bw);
        float inv = rsqrtf(ss * (1.0f / HH) + 1e-5f);
        float4 o1, o2;
        o1.x = fmaxf(ax * inv * g1.x + t1.x, 0.f);
        o1.y = fmaxf(ay * inv * g1.y + t1.y, 0.f);
        o1.z = fmaxf(az * inv * g1.z + t1.z, 0.f);
        o1.w = fmaxf(aw * inv * g1.w + t1.w, 0.f);
        o2.x = fmaxf(bx * inv * g2.x + t2.x, 0.f);
        o2.y = fmaxf(by * inv * g2.y + t2.y, 0.f);
        o2.z = fmaxf(bz * inv * g2.z + t2.z, 0.f);
        o2.w = fmaxf(bw * inv * g2.w + t2.w, 0.f);
        *reinterpret_cast<float4*>(&d_z[(size_t)r * HH + c1]) = o1;
        *reinterpret_cast<float4*>(&d_z[(size_t)r * HH + c2]) = o2;
    }
}

// ---------------- head: out[n, 0..1] = d_g[n] @ lin_W2 + lin_b2 ----------------
__global__ void k_head(const float* __restrict__ W, const float* __restrict__ b,
                       float* __restrict__ out) {
    int n = (blockIdx.x * blockDim.x + threadIdx.x) >> 5;
    if (n >= NN) return;
    int lane = threadIdx.x & 31;
    float4 v = *reinterpret_cast<const float4*>(&d_g[(size_t)n * DD + lane * 4]);
    float a0 = 0.f, a1 = 0.f;
    int d = lane * 4;
    a0 += v.x * W[(d + 0) * 2 + 0]; a1 += v.x * W[(d + 0) * 2 + 1];
    a0 += v.y * W[(d + 1) * 2 + 0]; a1 += v.y * W[(d + 1) * 2 + 1];
    a0 += v.z * W[(d + 2) * 2 + 0]; a1 += v.z * W[(d + 2) * 2 + 1];
    a0 += v.w * W[(d + 3) * 2 + 0]; a1 += v.w * W[(d + 3) * 2 + 1];
    a0 = warp_sum(a0);
    a1 = warp_sum(a1);
    if (lane == 0) {
        out[n * 2 + 0] = a0 + b[0];
        out[n * 2 + 1] = a1 + b[1];
    }
}

// ---------------- launch ----------------
#define OFF_ENC 0
#define OFF_W1(i) (16384 + (i) * 32768)
#define OFF_W2(i) (16384 + 6 * 32768 + (i) * 32768)
#define OFF_LIN (16384 + 12 * 32768)

extern "C" void kernel_launch(void* const* d_in, const int* in_sizes, int n_in,
                              void* d_out, int out_size) {
    const float* x     = (const float*)d_in[0];
    const void*  ei    = d_in[1];
    const float* enc_W = (const float*)d_in[2];
    const float* enc_b = (const float*)d_in[3];
    const float* ln_g  = (const float*)d_in[4];
    const float* ln_b  = (const float*)d_in[5];
    const float* tt    = (const float*)d_in[6];
    const float* W1    = (const float*)d_in[7];
    const float* b1    = (const float*)d_in[8];
    const float* mg    = (const float*)d_in[9];
    const float* mb    = (const float*)d_in[10];
    const float* W2    = (const float*)d_in[11];
    const float* b2    = (const float*)d_in[12];
    const float* lW1   = (const float*)d_in[13];
    const float* lb1   = (const float*)d_in[14];
    const float* lW2   = (const float*)d_in[15];
    const float* lb2   = (const float*)d_in[16];
    float* out = (float*)d_out;

    const int SM_STD  = 4 * 128 * ALD * 2;                       // 139264
    const int SM_MLP1 = (2 * 128 + 2 * 256) * ALD * 2;           // 208896
    cudaFuncSetAttribute(gemm_std<128, false, true,  false>, cudaFuncAttributeMaxDynamicSharedMemorySize, SM_STD);
    cudaFuncSetAttribute(gemm_std<256, true,  true,  false>, cudaFuncAttributeMaxDynamicSharedMemorySize, SM_STD);
    cudaFuncSetAttribute(gemm_std<256, true,  false, false>, cudaFuncAttributeMaxDynamicSharedMemorySize, SM_STD);
    cudaFuncSetAttribute(gemm_std<128, false, false, true >, cudaFuncAttributeMaxDynamicSharedMemorySize, SM_STD);
    cudaFuncSetAttribute(gemm_mlp1, cudaFuncAttributeMaxDynamicSharedMemorySize, SM_MLP1);

    // weight prep (single launch)
    k_tsplit_all<<<(WT_TOTAL + 255) / 256, 256>>>(enc_W, W1, W2, lW1);

    // CSR build
    k_probe<<<1, 256>>>(ei);
    k_zero_deg<<<(NN + 255) / 256, 256>>>();
    k_count<<<(EE + 255) / 256, 256>>>(ei);
    k_scan1<<<NSCB, SCB>>>();
    k_scan2<<<1, SCB>>>();
    k_scan3<<<NSCB, SCB>>>();
    k_fill<<<(EE + 255) / 256, 256>>>(ei);

    const int NWBLK = (NN * 32 + 255) / 256;
    const int MBLK = (NN + 127) / 128;  // 391

    // encoder: d_h = x @ enc_W + enc_b; fused msg precompute for layer 0
    gemm_std<128, false, true, false><<<MBLK, 256, SM_STD>>>(
        x, 0, OFF_ENC, enc_b, nullptr, 1, ln_g, ln_b, tt, 0);

    for (int i = 0; i < LL; i++) {
        k_agg<<<NWBLK, 256>>>();
        gemm_mlp1<<<MBLK, 512, SM_MLP1>>>(OFF_W1(i), b1 + i * HH, mg + i * HH, mb + i * HH);
        if (i < LL - 1) {
            gemm_std<256, true, true, false><<<MBLK, 256, SM_STD>>>(
                nullptr, 4, OFF_W2(i), b2 + i * DD, nullptr, 1,
                ln_g + (i + 1) * DD, ln_b + (i + 1) * DD, tt, i + 1);
        } else {
            gemm_std<256, true, false, false><<<MBLK, 256, SM_STD>>>(
                nullptr, 4, OFF_W2(i), b2 + i * DD, nullptr, 1, nullptr, nullptr, nullptr, 0);
        }
    }

    // head: d_g = relu(d_h @ lin_W1 + lin_b1); out = d_g @ lin_W2 + lin_b2
    gemm_std<128, false, false, true><<<MBLK, 256, SM_STD>>>(
        nullptr, 1, OFF_LIN, lb1, nullptr, 2, nullptr, nullptr, nullptr, 0);
    k_head<<<NWBLK, 256>>>(lW2, lb2, out);
}